// round 5
// baseline (speedup 1.0000x reference)
#include <cuda_runtime.h>
#include <cuda_bf16.h>
#include <cstdint>

#define Bb 2
#define Nn 128
#define Ll 128
#define Hh 8
#define Ee 64

// smem: six bf16 tiles, 128 rows x 64 cols, pitch 144B (36 banks ≡ 4 mod 32
// -> conflict-free ldmatrix). No aliasing: only ONE barrier needed.
#define QP 144
#define SQ_H 0
#define SQ_L 18432
#define SK_H 36864
#define SK_L 55296
#define SV_H 73728
#define SV_L 92160
#define SM_TOTAL 110592

// V_t stored packed: per element u32 = bf16_hi | bf16_lo<<16
__device__ uint32_t g_vt[(size_t)Bb * Nn * Ll * Hh * Ee];

// ---------------- helpers ----------------
__device__ __forceinline__ uint32_t smem_u32(const void* p) {
    uint32_t a;
    asm("{ .reg .u64 t; cvta.to.shared.u64 t, %1; cvt.u32.u64 %0, t; }"
        : "=r"(a) : "l"(p));
    return a;
}
__device__ __forceinline__ void ldsm4(uint32_t* r, uint32_t a) {
    asm volatile("ldmatrix.sync.aligned.m8n8.x4.shared.b16 {%0,%1,%2,%3}, [%4];"
                 : "=r"(r[0]), "=r"(r[1]), "=r"(r[2]), "=r"(r[3]) : "r"(a));
}
__device__ __forceinline__ void ldsm4t(uint32_t* r, uint32_t a) {
    asm volatile("ldmatrix.sync.aligned.m8n8.x4.trans.shared.b16 {%0,%1,%2,%3}, [%4];"
                 : "=r"(r[0]), "=r"(r[1]), "=r"(r[2]), "=r"(r[3]) : "r"(a));
}
__device__ __forceinline__ void mma16816(float* c, const uint32_t* a, const uint32_t* b) {
    asm volatile(
        "mma.sync.aligned.m16n8k16.row.col.f32.bf16.bf16.f32 "
        "{%0,%1,%2,%3}, {%4,%5,%6,%7}, {%8,%9}, {%0,%1,%2,%3};"
        : "+f"(c[0]), "+f"(c[1]), "+f"(c[2]), "+f"(c[3])
        : "r"(a[0]), "r"(a[1]), "r"(a[2]), "r"(a[3]), "r"(b[0]), "r"(b[1]));
}
__device__ __forceinline__ uint32_t cvt_bf16x2(float y, float x) {
    uint32_t r;
    asm("cvt.rn.bf16x2.f32 %0, %1, %2;" : "=r"(r) : "f"(y), "f"(x));
    return r;
}
// hi = truncated-bf16 pair (PRMT), lo = rn-bf16 of exact residuals
__device__ __forceinline__ void split_pair(float x, float y, uint32_t& hi, uint32_t& lo) {
    const uint32_t u0 = __float_as_uint(x), u1 = __float_as_uint(y);
    hi = __byte_perm(u0, u1, 0x7632);
    const float l0 = x - __uint_as_float(u0 & 0xFFFF0000u);
    const float l1 = y - __uint_as_float(u1 & 0xFFFF0000u);
    lo = cvt_bf16x2(l1, l0);
}

// ---------------------------------------------------------------------------
template <bool SPATIAL>
__global__ __launch_bounds__(256, 2)
void attn_mma_kernel(const float* __restrict__ q, const float* __restrict__ k,
                     const float* __restrict__ v32, const uint32_t* __restrict__ vpk,
                     const float* __restrict__ mask,
                     uint32_t* __restrict__ dst_pk, float* __restrict__ dst_f)
{
    extern __shared__ char sm[];
    const uint32_t sb = smem_u32(sm);
    const int t = threadIdx.x, lane = t & 31, wid = t >> 5;

    const int pid = blockIdx.x;
    const int h = pid & 7;
    const int rl = (pid >> 3) & 127;
    const int b = pid >> 10;
    int base, rstride;
    if (SPATIAL) { base = (b * Nn * Ll + rl) * (Hh * Ee) + h * Ee; rstride = Ll * Hh * Ee; }
    else         { base = ((b * Nn + rl) * Ll) * (Hh * Ee) + h * Ee; rstride = Hh * Ee; }

    // Q pre-scaled by softmax_scale * log2(e): exp(0.125 s) == exp2(QS s)
    const float QS = 0.125f * 1.44269504088896f;

    // ---- single load+convert pass: Q (scaled), K, V ----
#pragma unroll
    for (int i = 0; i < 16; i++) {
        const int idx = i * 256 + t;
        const int row = idx >> 5, e2 = idx & 31;
        const int go = base + row * rstride + e2 * 2;
        float2 qv = *(const float2*)(q + go);
        const float2 kv = *(const float2*)(k + go);
        qv.x *= QS; qv.y *= QS;
        const uint32_t off = (uint32_t)(row * QP + e2 * 4);
        uint32_t hi, lo;
        split_pair(qv.x, qv.y, hi, lo);
        *(uint32_t*)(sm + SQ_H + off) = hi; *(uint32_t*)(sm + SQ_L + off) = lo;
        split_pair(kv.x, kv.y, hi, lo);
        *(uint32_t*)(sm + SK_H + off) = hi; *(uint32_t*)(sm + SK_L + off) = lo;
        if (SPATIAL) {
            const uint2 w = *(const uint2*)(vpk + go);
            *(uint32_t*)(sm + SV_H + off) = __byte_perm(w.x, w.y, 0x5410);
            *(uint32_t*)(sm + SV_L + off) = __byte_perm(w.x, w.y, 0x7632);
        } else {
            const float2 vv = *(const float2*)(v32 + go);
            split_pair(vv.x, vv.y, hi, lo);
            *(uint32_t*)(sm + SV_H + off) = hi;
            *(uint32_t*)(sm + SV_L + off) = lo;
        }
    }
    __syncthreads();   // the only barrier in the kernel

    // ---- MMA1: S = Qh*Kh + Ql*Kh + Qh*Kl ; A hi+lo in regs, K frags loaded once ----
    const int r0 = wid * 16;
    float c[16][4];
#pragma unroll
    for (int nt = 0; nt < 16; nt++)
#pragma unroll
        for (int j = 0; j < 4; j++) c[nt][j] = 0.f;

    uint32_t ah[4][4], al[4][4];
    {
        const uint32_t arow_h = sb + SQ_H
            + (uint32_t)((r0 + (lane & 15)) * QP + (lane >> 4) * 16);
        const uint32_t arow_l = arow_h + (SQ_L - SQ_H);
#pragma unroll
        for (int ks = 0; ks < 4; ks++) {
            ldsm4(ah[ks], arow_h + ks * 32);
            ldsm4(al[ks], arow_l + ks * 32);
        }
    }
#pragma unroll
    for (int nt = 0; nt < 16; nt += 2) {
        const uint32_t brh = sb + SK_H
            + (uint32_t)((nt * 8 + (lane & 7)) * QP + ((lane >> 3) & 3) * 16);
        uint32_t b0[4], b1[4], d0[4], d1[4];
        // Kh fragments for rows [nt*8, nt*8+16)
        ldsm4(b0, brh); ldsm4(b1, brh + 64);
        ldsm4(d0, brh + 8 * QP); ldsm4(d1, brh + 8 * QP + 64);
        // Qh*Kh
        mma16816(c[nt], ah[0], b0);     mma16816(c[nt + 1], ah[0], d0);
        mma16816(c[nt], ah[1], b0 + 2); mma16816(c[nt + 1], ah[1], d0 + 2);
        mma16816(c[nt], ah[2], b1);     mma16816(c[nt + 1], ah[2], d1);
        mma16816(c[nt], ah[3], b1 + 2); mma16816(c[nt + 1], ah[3], d1 + 2);
        // Ql*Kh
        mma16816(c[nt], al[0], b0);     mma16816(c[nt + 1], al[0], d0);
        mma16816(c[nt], al[1], b0 + 2); mma16816(c[nt + 1], al[1], d0 + 2);
        mma16816(c[nt], al[2], b1);     mma16816(c[nt + 1], al[2], d1);
        mma16816(c[nt], al[3], b1 + 2); mma16816(c[nt + 1], al[3], d1 + 2);
        // Kl fragments (reuse regs)
        const uint32_t brl = brh + (SK_L - SK_H);
        ldsm4(b0, brl); ldsm4(b1, brl + 64);
        ldsm4(d0, brl + 8 * QP); ldsm4(d1, brl + 8 * QP + 64);
        // Qh*Kl
        mma16816(c[nt], ah[0], b0);     mma16816(c[nt + 1], ah[0], d0);
        mma16816(c[nt], ah[1], b0 + 2); mma16816(c[nt + 1], ah[1], d0 + 2);
        mma16816(c[nt], ah[2], b1);     mma16816(c[nt + 1], ah[2], d1);
        mma16816(c[nt], ah[3], b1 + 2); mma16816(c[nt + 1], ah[3], d1 + 2);
    }

    // ---- mask (spatial) + softmax (no max pass; logits are small) ----
    const int row_lo = r0 + (lane >> 2);
    const int row_hi = row_lo + 8;
    if (SPATIAL) {
        const float* mrow_lo = mask + ((size_t)b * Nn + row_lo) * Nn;
        const float* mrow_hi = mask + ((size_t)b * Nn + row_hi) * Nn;
#pragma unroll
        for (int nt = 0; nt < 16; nt++) {
            const int col = nt * 8 + (lane & 3) * 2;
            const float2 ml = *(const float2*)(mrow_lo + col);
            const float2 mh = *(const float2*)(mrow_hi + col);
            c[nt][0] *= ml.x; c[nt][1] *= ml.y;
            c[nt][2] *= mh.x; c[nt][3] *= mh.y;
        }
    }
    float slo = 0.f, shi = 0.f;
#pragma unroll
    for (int nt = 0; nt < 16; nt++) {
        c[nt][0] = exp2f(c[nt][0]);
        c[nt][1] = exp2f(c[nt][1]);
        c[nt][2] = exp2f(c[nt][2]);
        c[nt][3] = exp2f(c[nt][3]);
        slo += c[nt][0] + c[nt][1];
        shi += c[nt][2] + c[nt][3];
    }
    slo += __shfl_xor_sync(0xFFFFFFFF, slo, 1);
    slo += __shfl_xor_sync(0xFFFFFFFF, slo, 2);
    shi += __shfl_xor_sync(0xFFFFFFFF, shi, 1);
    shi += __shfl_xor_sync(0xFFFFFFFF, shi, 2);
    const float invlo = 1.0f / slo, invhi = 1.0f / shi;

    // ---- convert P to A-fragments in registers (C-frag == A-frag layout) ----
    uint32_t ph[32], pl[32];
#pragma unroll
    for (int kt = 0; kt < 8; kt++) {
        split_pair(c[2 * kt][0],     c[2 * kt][1],     ph[kt * 4 + 0], pl[kt * 4 + 0]);
        split_pair(c[2 * kt][2],     c[2 * kt][3],     ph[kt * 4 + 1], pl[kt * 4 + 1]);
        split_pair(c[2 * kt + 1][0], c[2 * kt + 1][1], ph[kt * 4 + 2], pl[kt * 4 + 2]);
        split_pair(c[2 * kt + 1][2], c[2 * kt + 1][3], ph[kt * 4 + 3], pl[kt * 4 + 3]);
    }

    // ---- MMA2: O = Ph*Vh + Pl*Vh + Ph*Vl  (A in regs; V already resident) ----
    float o[8][4];
#pragma unroll
    for (int nt = 0; nt < 8; nt++)
#pragma unroll
        for (int j = 0; j < 4; j++) o[nt][j] = 0.f;

    const uint32_t vsel = (uint32_t)(((lane & 7) + ((lane >> 3) & 1) * 8) * QP
                                     + ((lane >> 4) & 1) * 16);
#pragma unroll
    for (int ks = 0; ks < 8; ks++) {
        const uint32_t* a_h = ph + ks * 4;
        const uint32_t* a_l = pl + ks * 4;
        const uint32_t bh0 = sb + SV_H + (uint32_t)(ks * 16 * QP) + vsel;
        const uint32_t bl0 = bh0 + (SV_L - SV_H);
#pragma unroll
        for (int p = 0; p < 4; p++) {
            uint32_t bb[4];
            ldsm4t(bb, bh0 + p * 32);
            mma16816(o[2 * p],     a_h, bb);
            mma16816(o[2 * p + 1], a_h, bb + 2);
            mma16816(o[2 * p],     a_l, bb);
            mma16816(o[2 * p + 1], a_l, bb + 2);
        }
#pragma unroll
        for (int p = 0; p < 4; p++) {
            uint32_t bb[4];
            ldsm4t(bb, bl0 + p * 32);
            mma16816(o[2 * p],     a_h, bb);
            mma16816(o[2 * p + 1], a_h, bb + 2);
        }
    }

    // ---- epilogue ----
    if (SPATIAL) {
        float* orow_lo = dst_f + base + row_lo * rstride;
        float* orow_hi = dst_f + base + row_hi * rstride;
#pragma unroll
        for (int nt = 0; nt < 8; nt++) {
            const int col = nt * 8 + (lane & 3) * 2;
            *(float2*)(orow_lo + col) = make_float2(o[nt][0] * invlo, o[nt][1] * invlo);
            *(float2*)(orow_hi + col) = make_float2(o[nt][2] * invhi, o[nt][3] * invhi);
        }
    } else {
        uint32_t* orow_lo = dst_pk + base + row_lo * rstride;
        uint32_t* orow_hi = dst_pk + base + row_hi * rstride;
#pragma unroll
        for (int nt = 0; nt < 8; nt++) {
            const int col = nt * 8 + (lane & 3) * 2;
            {
                const float f0 = o[nt][0] * invlo, f1 = o[nt][1] * invlo;
                const uint32_t u0 = __float_as_uint(f0), u1 = __float_as_uint(f1);
                const float l0 = f0 - __uint_as_float(u0 & 0xFFFF0000u);
                const float l1 = f1 - __uint_as_float(u1 & 0xFFFF0000u);
                const uint32_t lop = cvt_bf16x2(l1, l0);
                uint2 w;
                w.x = __byte_perm(u0, lop, 0x5432);
                w.y = __byte_perm(u1, lop, 0x7632);
                *(uint2*)(orow_lo + col) = w;
            }
            {
                const float f0 = o[nt][2] * invhi, f1 = o[nt][3] * invhi;
                const uint32_t u0 = __float_as_uint(f0), u1 = __float_as_uint(f1);
                const float l0 = f0 - __uint_as_float(u0 & 0xFFFF0000u);
                const float l1 = f1 - __uint_as_float(u1 & 0xFFFF0000u);
                const uint32_t lop = cvt_bf16x2(l1, l0);
                uint2 w;
                w.x = __byte_perm(u0, lop, 0x5432);
                w.y = __byte_perm(u1, lop, 0x7632);
                *(uint2*)(orow_hi + col) = w;
            }
        }
    }
}

// ---------------------------------------------------------------------------
extern "C" void kernel_launch(void* const* d_in, const int* in_sizes, int n_in,
                              void* d_out, int out_size)
{
    const float* q    = (const float*)d_in[0];
    const float* k    = (const float*)d_in[1];
    const float* v    = (const float*)d_in[2];
    const float* mask = (const float*)d_in[3];
    float* out = (float*)d_out;

    uint32_t* vt;
    cudaGetSymbolAddress((void**)&vt, g_vt);

    cudaFuncSetAttribute(attn_mma_kernel<false>,
                         cudaFuncAttributeMaxDynamicSharedMemorySize, SM_TOTAL);
    cudaFuncSetAttribute(attn_mma_kernel<true>,
                         cudaFuncAttributeMaxDynamicSharedMemorySize, SM_TOTAL);

    attn_mma_kernel<false><<<Bb * Nn * Hh, 256, SM_TOTAL>>>(
        q, k, v, nullptr, nullptr, vt, nullptr);
    attn_mma_kernel<true><<<Bb * Ll * Hh, 256, SM_TOTAL>>>(
        q, k, nullptr, (const uint32_t*)vt, mask, nullptr, out);
}

// round 6
// speedup vs baseline: 1.1645x; 1.1645x over previous
#include <cuda_runtime.h>
#include <cuda_bf16.h>
#include <cstdint>

#define Bb 2
#define Nn 128
#define Ll 128
#define Hh 8
#define Ee 64

// smem: Q/K bf16 hi/lo tiles, 128 rows x 64 cols, pitch 144B (36 banks ≡ 4 mod 32
// -> conflict-free ldmatrix). V hi/lo overwrites the Q region after MMA1.
#define QP 144
#define SQ_H 0
#define SQ_L 18432
#define SK_H 36864
#define SK_L 55296
#define SM_TOTAL 73728
#define SV_H 0
#define SV_L 18432

// V_t stored packed: per element u32 = bf16_hi | bf16_lo<<16
__device__ uint32_t g_vt[(size_t)Bb * Nn * Ll * Hh * Ee];

// ---------------- helpers ----------------
__device__ __forceinline__ uint32_t smem_u32(const void* p) {
    uint32_t a;
    asm("{ .reg .u64 t; cvta.to.shared.u64 t, %1; cvt.u32.u64 %0, t; }"
        : "=r"(a) : "l"(p));
    return a;
}
__device__ __forceinline__ void ldsm4(uint32_t* r, uint32_t a) {
    asm volatile("ldmatrix.sync.aligned.m8n8.x4.shared.b16 {%0,%1,%2,%3}, [%4];"
                 : "=r"(r[0]), "=r"(r[1]), "=r"(r[2]), "=r"(r[3]) : "r"(a));
}
__device__ __forceinline__ void ldsm4t(uint32_t* r, uint32_t a) {
    asm volatile("ldmatrix.sync.aligned.m8n8.x4.trans.shared.b16 {%0,%1,%2,%3}, [%4];"
                 : "=r"(r[0]), "=r"(r[1]), "=r"(r[2]), "=r"(r[3]) : "r"(a));
}
__device__ __forceinline__ void mma16816(float* c, const uint32_t* a, const uint32_t* b) {
    asm volatile(
        "mma.sync.aligned.m16n8k16.row.col.f32.bf16.bf16.f32 "
        "{%0,%1,%2,%3}, {%4,%5,%6,%7}, {%8,%9}, {%0,%1,%2,%3};"
        : "+f"(c[0]), "+f"(c[1]), "+f"(c[2]), "+f"(c[3])
        : "r"(a[0]), "r"(a[1]), "r"(a[2]), "r"(a[3]), "r"(b[0]), "r"(b[1]));
}
__device__ __forceinline__ uint32_t cvt_bf16x2(float y, float x) {
    uint32_t r;
    asm("cvt.rn.bf16x2.f32 %0, %1, %2;" : "=r"(r) : "f"(y), "f"(x));
    return r;
}
// hi = truncated-bf16 pair (PRMT), lo = rn-bf16 of exact residuals
__device__ __forceinline__ void split_pair(float x, float y, uint32_t& hi, uint32_t& lo) {
    const uint32_t u0 = __float_as_uint(x), u1 = __float_as_uint(y);
    hi = __byte_perm(u0, u1, 0x7632);
    const float l0 = x - __uint_as_float(u0 & 0xFFFF0000u);
    const float l1 = y - __uint_as_float(u1 & 0xFFFF0000u);
    lo = cvt_bf16x2(l1, l0);
}

// ---------------------------------------------------------------------------
template <bool SPATIAL>
__global__ __launch_bounds__(256, 2)
void attn_mma_kernel(const float* __restrict__ q, const float* __restrict__ k,
                     const float* __restrict__ v32, const uint32_t* __restrict__ vpk,
                     const float* __restrict__ mask,
                     uint32_t* __restrict__ dst_pk, float* __restrict__ dst_f)
{
    extern __shared__ char sm[];
    const uint32_t sb = smem_u32(sm);
    const int t = threadIdx.x, lane = t & 31, wid = t >> 5;

    const int pid = blockIdx.x;
    const int h = pid & 7;
    const int rl = (pid >> 3) & 127;
    const int b = pid >> 10;
    int base, rstride;
    if (SPATIAL) { base = (b * Nn * Ll + rl) * (Hh * Ee) + h * Ee; rstride = Ll * Hh * Ee; }
    else         { base = ((b * Nn + rl) * Ll) * (Hh * Ee) + h * Ee; rstride = Hh * Ee; }

    // Q pre-scaled by softmax_scale * log2(e): exp(0.125 s) == exp2(QS s)
    const float QS = 0.125f * 1.44269504088896f;

    // ---- load + convert Q (scaled), K ----
#pragma unroll
    for (int i = 0; i < 16; i++) {
        const int idx = i * 256 + t;
        const int row = idx >> 5, e2 = idx & 31;
        const int go = base + row * rstride + e2 * 2;
        float2 qv = *(const float2*)(q + go);
        const float2 kv = *(const float2*)(k + go);
        qv.x *= QS; qv.y *= QS;
        const uint32_t off = (uint32_t)(row * QP + e2 * 4);
        uint32_t hi, lo;
        split_pair(qv.x, qv.y, hi, lo);
        *(uint32_t*)(sm + SQ_H + off) = hi; *(uint32_t*)(sm + SQ_L + off) = lo;
        split_pair(kv.x, kv.y, hi, lo);
        *(uint32_t*)(sm + SK_H + off) = hi; *(uint32_t*)(sm + SK_L + off) = lo;
    }
    __syncthreads();

    // ---- MMA1: S = Qh*Kh + Ql*Kh + Qh*Kl ; Qh+Ql frags in regs, K frags once ----
    const int r0 = wid * 16;
    float c[16][4];
#pragma unroll
    for (int nt = 0; nt < 16; nt++)
#pragma unroll
        for (int j = 0; j < 4; j++) c[nt][j] = 0.f;

    uint32_t ah[4][4], al[4][4];
    {
        const uint32_t arow_h = sb + SQ_H
            + (uint32_t)((r0 + (lane & 15)) * QP + (lane >> 4) * 16);
        const uint32_t arow_l = arow_h + (SQ_L - SQ_H);
#pragma unroll
        for (int ks = 0; ks < 4; ks++) {
            ldsm4(ah[ks], arow_h + ks * 32);
            ldsm4(al[ks], arow_l + ks * 32);
        }
    }
#pragma unroll
    for (int nt = 0; nt < 16; nt += 2) {
        const uint32_t brh = sb + SK_H
            + (uint32_t)((nt * 8 + (lane & 7)) * QP + ((lane >> 3) & 3) * 16);
        uint32_t b0[4], b1[4], d0[4], d1[4];
        // Kh fragments for rows [nt*8, nt*8+16)
        ldsm4(b0, brh); ldsm4(b1, brh + 64);
        ldsm4(d0, brh + 8 * QP); ldsm4(d1, brh + 8 * QP + 64);
        // Qh*Kh
        mma16816(c[nt], ah[0], b0);     mma16816(c[nt + 1], ah[0], d0);
        mma16816(c[nt], ah[1], b0 + 2); mma16816(c[nt + 1], ah[1], d0 + 2);
        mma16816(c[nt], ah[2], b1);     mma16816(c[nt + 1], ah[2], d1);
        mma16816(c[nt], ah[3], b1 + 2); mma16816(c[nt + 1], ah[3], d1 + 2);
        // Ql*Kh
        mma16816(c[nt], al[0], b0);     mma16816(c[nt + 1], al[0], d0);
        mma16816(c[nt], al[1], b0 + 2); mma16816(c[nt + 1], al[1], d0 + 2);
        mma16816(c[nt], al[2], b1);     mma16816(c[nt + 1], al[2], d1);
        mma16816(c[nt], al[3], b1 + 2); mma16816(c[nt + 1], al[3], d1 + 2);
        // Kl fragments (reuse regs)
        const uint32_t brl = brh + (SK_L - SK_H);
        ldsm4(b0, brl); ldsm4(b1, brl + 64);
        ldsm4(d0, brl + 8 * QP); ldsm4(d1, brl + 8 * QP + 64);
        // Qh*Kl
        mma16816(c[nt], ah[0], b0);     mma16816(c[nt + 1], ah[0], d0);
        mma16816(c[nt], ah[1], b0 + 2); mma16816(c[nt + 1], ah[1], d0 + 2);
        mma16816(c[nt], ah[2], b1);     mma16816(c[nt + 1], ah[2], d1);
        mma16816(c[nt], ah[3], b1 + 2); mma16816(c[nt + 1], ah[3], d1 + 2);
    }
    __syncthreads();   // Q,K reads done -> V may overwrite Q region

    // ---- V into smem (overwrites Q region); LDG latency overlaps softmax ----
#pragma unroll
    for (int i = 0; i < 16; i++) {
        const int idx = i * 256 + t;
        const int row = idx >> 5, e2 = idx & 31;
        const uint32_t off = (uint32_t)(row * QP + e2 * 4);
        if (SPATIAL) {
            const uint2 w = *(const uint2*)(vpk + base + row * rstride + e2 * 2);
            *(uint32_t*)(sm + SV_H + off) = __byte_perm(w.x, w.y, 0x5410);
            *(uint32_t*)(sm + SV_L + off) = __byte_perm(w.x, w.y, 0x7632);
        } else {
            const float2 vv = *(const float2*)(v32 + base + row * rstride + e2 * 2);
            uint32_t hi, lo;
            split_pair(vv.x, vv.y, hi, lo);
            *(uint32_t*)(sm + SV_H + off) = hi;
            *(uint32_t*)(sm + SV_L + off) = lo;
        }
    }

    // ---- mask (spatial) + softmax (no max pass; logits are small) ----
    const int row_lo = r0 + (lane >> 2);
    const int row_hi = row_lo + 8;
    if (SPATIAL) {
        const float* mrow_lo = mask + ((size_t)b * Nn + row_lo) * Nn;
        const float* mrow_hi = mask + ((size_t)b * Nn + row_hi) * Nn;
#pragma unroll
        for (int nt = 0; nt < 16; nt++) {
            const int col = nt * 8 + (lane & 3) * 2;
            const float2 ml = *(const float2*)(mrow_lo + col);
            const float2 mh = *(const float2*)(mrow_hi + col);
            c[nt][0] *= ml.x; c[nt][1] *= ml.y;
            c[nt][2] *= mh.x; c[nt][3] *= mh.y;
        }
    }
    float slo = 0.f, shi = 0.f;
#pragma unroll
    for (int nt = 0; nt < 16; nt++) {
        c[nt][0] = exp2f(c[nt][0]);
        c[nt][1] = exp2f(c[nt][1]);
        c[nt][2] = exp2f(c[nt][2]);
        c[nt][3] = exp2f(c[nt][3]);
        slo += c[nt][0] + c[nt][1];
        shi += c[nt][2] + c[nt][3];
    }
    slo += __shfl_xor_sync(0xFFFFFFFF, slo, 1);
    slo += __shfl_xor_sync(0xFFFFFFFF, slo, 2);
    shi += __shfl_xor_sync(0xFFFFFFFF, shi, 1);
    shi += __shfl_xor_sync(0xFFFFFFFF, shi, 2);
    const float invlo = 1.0f / slo, invhi = 1.0f / shi;

    // ---- convert P to A-fragments in registers (C-frag == A-frag layout) ----
    uint32_t ph[32], pl[32];
#pragma unroll
    for (int kt = 0; kt < 8; kt++) {
        split_pair(c[2 * kt][0],     c[2 * kt][1],     ph[kt * 4 + 0], pl[kt * 4 + 0]);
        split_pair(c[2 * kt][2],     c[2 * kt][3],     ph[kt * 4 + 1], pl[kt * 4 + 1]);
        split_pair(c[2 * kt + 1][0], c[2 * kt + 1][1], ph[kt * 4 + 2], pl[kt * 4 + 2]);
        split_pair(c[2 * kt + 1][2], c[2 * kt + 1][3], ph[kt * 4 + 3], pl[kt * 4 + 3]);
    }
    __syncthreads();   // V tiles ready

    // ---- MMA2: O = Ph*Vh + Pl*Vh + Ph*Vl  (A in registers, B via ldsm4t) ----
    float o[8][4];
#pragma unroll
    for (int nt = 0; nt < 8; nt++)
#pragma unroll
        for (int j = 0; j < 4; j++) o[nt][j] = 0.f;

    const uint32_t vsel = (uint32_t)(((lane & 7) + ((lane >> 3) & 1) * 8) * QP
                                     + ((lane >> 4) & 1) * 16);
#pragma unroll
    for (int ks = 0; ks < 8; ks++) {
        const uint32_t* a_h = ph + ks * 4;
        const uint32_t* a_l = pl + ks * 4;
        const uint32_t bh0 = sb + SV_H + (uint32_t)(ks * 16 * QP) + vsel;
        const uint32_t bl0 = bh0 + (SV_L - SV_H);
#pragma unroll
        for (int p = 0; p < 4; p++) {
            uint32_t bb[4];
            ldsm4t(bb, bh0 + p * 32);
            mma16816(o[2 * p],     a_h, bb);
            mma16816(o[2 * p + 1], a_h, bb + 2);
            mma16816(o[2 * p],     a_l, bb);
            mma16816(o[2 * p + 1], a_l, bb + 2);
        }
#pragma unroll
        for (int p = 0; p < 4; p++) {
            uint32_t bb[4];
            ldsm4t(bb, bl0 + p * 32);
            mma16816(o[2 * p],     a_h, bb);
            mma16816(o[2 * p + 1], a_h, bb + 2);
        }
    }

    // ---- epilogue ----
    if (SPATIAL) {
        float* orow_lo = dst_f + base + row_lo * rstride;
        float* orow_hi = dst_f + base + row_hi * rstride;
#pragma unroll
        for (int nt = 0; nt < 8; nt++) {
            const int col = nt * 8 + (lane & 3) * 2;
            *(float2*)(orow_lo + col) = make_float2(o[nt][0] * invlo, o[nt][1] * invlo);
            *(float2*)(orow_hi + col) = make_float2(o[nt][2] * invhi, o[nt][3] * invhi);
        }
    } else {
        uint32_t* orow_lo = dst_pk + base + row_lo * rstride;
        uint32_t* orow_hi = dst_pk + base + row_hi * rstride;
#pragma unroll
        for (int nt = 0; nt < 8; nt++) {
            const int col = nt * 8 + (lane & 3) * 2;
            {
                const float f0 = o[nt][0] * invlo, f1 = o[nt][1] * invlo;
                const uint32_t u0 = __float_as_uint(f0), u1 = __float_as_uint(f1);
                const float l0 = f0 - __uint_as_float(u0 & 0xFFFF0000u);
                const float l1 = f1 - __uint_as_float(u1 & 0xFFFF0000u);
                const uint32_t lop = cvt_bf16x2(l1, l0);
                uint2 w;
                w.x = __byte_perm(u0, lop, 0x5432);
                w.y = __byte_perm(u1, lop, 0x7632);
                *(uint2*)(orow_lo + col) = w;
            }
            {
                const float f0 = o[nt][2] * invhi, f1 = o[nt][3] * invhi;
                const uint32_t u0 = __float_as_uint(f0), u1 = __float_as_uint(f1);
                const float l0 = f0 - __uint_as_float(u0 & 0xFFFF0000u);
                const float l1 = f1 - __uint_as_float(u1 & 0xFFFF0000u);
                const uint32_t lop = cvt_bf16x2(l1, l0);
                uint2 w;
                w.x = __byte_perm(u0, lop, 0x5432);
                w.y = __byte_perm(u1, lop, 0x7632);
                *(uint2*)(orow_hi + col) = w;
            }
        }
    }
}

// ---------------------------------------------------------------------------
extern "C" void kernel_launch(void* const* d_in, const int* in_sizes, int n_in,
                              void* d_out, int out_size)
{
    const float* q    = (const float*)d_in[0];
    const float* k    = (const float*)d_in[1];
    const float* v    = (const float*)d_in[2];
    const float* mask = (const float*)d_in[3];
    float* out = (float*)d_out;

    uint32_t* vt;
    cudaGetSymbolAddress((void**)&vt, g_vt);

    cudaFuncSetAttribute(attn_mma_kernel<false>,
                         cudaFuncAttributeMaxDynamicSharedMemorySize, SM_TOTAL);
    cudaFuncSetAttribute(attn_mma_kernel<true>,
                         cudaFuncAttributeMaxDynamicSharedMemorySize, SM_TOTAL);

    attn_mma_kernel<false><<<Bb * Nn * Hh, 256, SM_TOTAL>>>(
        q, k, v, nullptr, nullptr, vt, nullptr);
    attn_mma_kernel<true><<<Bb * Ll * Hh, 256, SM_TOTAL>>>(
        q, k, nullptr, (const uint32_t*)vt, mask, nullptr, out);
}